// round 4
// baseline (speedup 1.0000x reference)
#include <cuda_runtime.h>
#include <cuda_bf16.h>

#define HID 256
#define GAMMA_F 12.0f
#define BATCH 8

typedef unsigned long long u64;

__device__ float g_scores[BATCH * 100000];  // S[e*8+b], 3.2MB (L2-resident)

__device__ __forceinline__ u64 ffma2(u64 a, u64 b, u64 c) {
    u64 d;
    asm("fma.rn.f32x2 %0, %1, %2, %3;" : "=l"(d) : "l"(a), "l"(b), "l"(c));
    return d;
}
__device__ __forceinline__ u64 fadd2(u64 a, u64 b) {
    u64 d;
    asm("add.rn.f32x2 %0, %1, %2;" : "=l"(d) : "l"(a), "l"(b));
    return d;
}
__device__ __forceinline__ u64 pack2(float lo, float hi) {
    u64 d;
    asm("mov.b64 %0, {%1, %2};" : "=l"(d) : "f"(lo), "f"(hi));
    return d;
}
__device__ __forceinline__ float2 unpack2(u64 v) {
    float2 r;
    asm("mov.b64 {%0, %1}, %2;" : "=f"(r.x), "=f"(r.y) : "l"(v));
    return r;
}

#define ABSMASK2 0x7FFFFFFF7FFFFFFFULL
#define NEG1X2   0xBF800000BF800000ULL

// ---------------------------------------------------------------------------
// Phase 1: stream entity table once; score all 8 hr vectors per row.
// Warp per row; lane owns dims [lane*8, lane*8+8) as 4 f32x2 pairs.
// ---------------------------------------------------------------------------
__global__ void __launch_bounds__(256, 2)
score_all_kernel(const float* __restrict__ ent,
                 const float* __restrict__ rel,
                 const int*   __restrict__ pos,
                 float*       __restrict__ scores,
                 int ne)
{
    const int lane = threadIdx.x & 31;
    const int warp = threadIdx.x >> 5;

    // hr = head + relation, packed: hr2[b][p] = dims (p*2, p*2+1) of lane's 8.
    u64 hr2[BATCH][4];
#pragma unroll
    for (int b = 0; b < BATCH; b++) {
        const int hidx = pos[b * 3 + 0];
        const int ridx = pos[b * 3 + 1];
        const float4* h4 = reinterpret_cast<const float4*>(ent + (size_t)hidx * HID);
        const float4* r4 = reinterpret_cast<const float4*>(rel + (size_t)ridx * HID);
        float4 h0 = h4[lane * 2], h1 = h4[lane * 2 + 1];
        float4 r0 = r4[lane * 2], r1 = r4[lane * 2 + 1];
        hr2[b][0] = pack2(h0.x + r0.x, h0.y + r0.y);
        hr2[b][1] = pack2(h0.z + r0.z, h0.w + r0.w);
        hr2[b][2] = pack2(h1.x + r1.x, h1.y + r1.y);
        hr2[b][3] = pack2(h1.z + r1.z, h1.w + r1.w);
    }

    const bool hi16 = (lane & 16) != 0;
    const bool hi8  = (lane & 8)  != 0;
    const bool hi4  = (lane & 4)  != 0;

    const int gw = blockIdx.x * (blockDim.x >> 5) + warp;
    const int nw = gridDim.x * (blockDim.x >> 5);

    int row = gw;
    ulonglong2 e0, e1, p0, p1;
    if (row < ne) {
        const ulonglong2* er = reinterpret_cast<const ulonglong2*>(ent + (size_t)row * HID);
        e0 = er[lane * 2];  e1 = er[lane * 2 + 1];
    }

    while (row < ne) {
        const int nxt = row + nw;
        if (nxt < ne) {  // prefetch next row
            const ulonglong2* pr = reinterpret_cast<const ulonglong2*>(ent + (size_t)nxt * HID);
            p0 = pr[lane * 2];  p1 = pr[lane * 2 + 1];
        }

        const u64 e2[4] = { e0.x, e0.y, e1.x, e1.y };

        float v[BATCH];
#pragma unroll
        for (int b = 0; b < BATCH; b++) {
            u64 acc = 0;  // (+0.0, +0.0)
#pragma unroll
            for (int p = 0; p < 4; p++) {
                const u64 d2 = ffma2(e2[p], NEG1X2, hr2[b][p]);  // hr - e
                acc = fadd2(acc, d2 & ABSMASK2);                  // += |d|
            }
            const float2 a = unpack2(acc);
            v[b] = a.x + a.y;
        }

        // Folding reduction: lane group (lane>>2) ends with sum for batch
        // (lane>>2); 9 shuffles total.
#pragma unroll
        for (int j = 0; j < 4; j++) {
            const float send = hi16 ? v[j] : v[j + 4];
            const float recv = __shfl_xor_sync(0xFFFFFFFFu, send, 16);
            v[j] = (hi16 ? v[j + 4] : v[j]) + recv;
        }
#pragma unroll
        for (int j = 0; j < 2; j++) {
            const float send = hi8 ? v[j] : v[j + 2];
            const float recv = __shfl_xor_sync(0xFFFFFFFFu, send, 8);
            v[j] = (hi8 ? v[j + 2] : v[j]) + recv;
        }
        {
            const float send = hi4 ? v[0] : v[1];
            const float recv = __shfl_xor_sync(0xFFFFFFFFu, send, 4);
            v[0] = (hi4 ? v[1] : v[0]) + recv;
        }
        v[0] += __shfl_xor_sync(0xFFFFFFFFu, v[0], 2);
        v[0] += __shfl_xor_sync(0xFFFFFFFFu, v[0], 1);

        if ((lane & 3) == 0)
            scores[(size_t)row * BATCH + (lane >> 2)] = GAMMA_F - v[0];

        e0 = p0;  e1 = p1;
        row = nxt;
    }
}

// ---------------------------------------------------------------------------
// Phase 2: out[b][n] = scores[neg[b][n]*8 + b]. 8 gathers per thread (ILP).
// ---------------------------------------------------------------------------
__global__ void __launch_bounds__(256)
gather_kernel(const float* __restrict__ scores,
              const int*   __restrict__ neg,
              float*       __restrict__ out,
              int nneg)
{
    const int b = blockIdx.y;
    const int t = blockIdx.x * blockDim.x + threadIdx.x;
    const int n4 = nneg >> 2;
    const int base = t * 2;
    if (base >= n4) return;

    const int4* nrow = reinterpret_cast<const int4*>(neg + (size_t)b * nneg);
    float4*     orow = reinterpret_cast<float4*>(out + (size_t)b * nneg);

    const int4 i0 = nrow[base];
    const bool have2 = (base + 1) < n4;
    const int4 i1 = have2 ? nrow[base + 1] : i0;

    float4 r0, r1;
    r0.x = scores[(size_t)i0.x * BATCH + b];
    r0.y = scores[(size_t)i0.y * BATCH + b];
    r0.z = scores[(size_t)i0.z * BATCH + b];
    r0.w = scores[(size_t)i0.w * BATCH + b];
    r1.x = scores[(size_t)i1.x * BATCH + b];
    r1.y = scores[(size_t)i1.y * BATCH + b];
    r1.z = scores[(size_t)i1.z * BATCH + b];
    r1.w = scores[(size_t)i1.w * BATCH + b];

    orow[base] = r0;
    if (have2) orow[base + 1] = r1;
}

extern "C" void kernel_launch(void* const* d_in, const int* in_sizes, int n_in,
                              void* d_out, int out_size)
{
    const float* ent = (const float*)d_in[0];  // [NE, 256] f32
    const float* rel = (const float*)d_in[1];  // [NR, 256] f32
    const int*   pos = (const int*)d_in[2];    // [B, 3] i32
    const int*   neg = (const int*)d_in[3];    // [B, N] i32
    float*       out = (float*)d_out;          // [B, N] f32

    const int batch = in_sizes[2] / 3;         // 8
    const int nneg  = in_sizes[3] / batch;     // 100000
    const int ne    = in_sizes[0] / HID;       // 100000

    float* scores;
    cudaGetSymbolAddress((void**)&scores, g_scores);

    score_all_kernel<<<296, 256>>>(ent, rel, pos, scores, ne);

    const int n8 = (nneg + 7) / 8;             // elems per thread = 8
    dim3 g2((n8 + 255) / 256, batch);
    gather_kernel<<<g2, 256>>>(scores, neg, out, nneg);
}